// round 5
// baseline (speedup 1.0000x reference)
#include <cuda_runtime.h>

// QMessagePassing: N=50000 nodes, E=800000 edges, F=16 per quaternion component.
// Strategy: build CSR-by-dst every call (hist + scan + scatter, int atomics only),
// then one fused kernel: per-node gather, softmax-weighted aggregation without the
// max pass (safe: |z| <~ 8.5 -> exp <= ~5e3, no overflow; softmax is shift-invariant),
// residual, and 2-layer quaternion MLP with compile-time sign folding.

#define Nn 50000
#define Ee 800000
#define Ff 16

// Scratch (no cudaMalloc allowed) — ~7 MB static device memory.
__device__ int  g_cnt[Nn];
__device__ int  g_off[Nn + 1];
__device__ int  g_pos[Nn];
__device__ int2 g_edges[Ee];   // (edge_id, src)

__global__ void k_zero() {
    int i = blockIdx.x * blockDim.x + threadIdx.x;
    if (i < Nn) g_cnt[i] = 0;
}

__global__ void k_hist(const int* __restrict__ dst) {
    int i = blockIdx.x * blockDim.x + threadIdx.x;
    if (i < Ee) atomicAdd(&g_cnt[dst[i]], 1);
}

#define SCAN_T 1024
#define SCAN_ITEMS 49   // 1024*49 = 50176 >= 50000
__global__ void k_scan() {
    __shared__ int ss[SCAN_T];
    int tid = threadIdx.x;
    int base = tid * SCAN_ITEMS;
    int loc[SCAN_ITEMS];
    int s = 0;
#pragma unroll
    for (int i = 0; i < SCAN_ITEMS; i++) {
        int idx = base + i;
        int v = (idx < Nn) ? g_cnt[idx] : 0;
        loc[i] = s;
        s += v;
    }
    ss[tid] = s;
    __syncthreads();
    // Hillis-Steele inclusive scan over 1024 partials
    for (int d = 1; d < SCAN_T; d <<= 1) {
        int v = (tid >= d) ? ss[tid - d] : 0;
        __syncthreads();
        ss[tid] += v;
        __syncthreads();
    }
    int prefix = (tid > 0) ? ss[tid - 1] : 0;
#pragma unroll
    for (int i = 0; i < SCAN_ITEMS; i++) {
        int idx = base + i;
        if (idx < Nn) {
            int o = prefix + loc[i];
            g_off[idx] = o;
            g_pos[idx] = o;
        }
    }
    if (tid == SCAN_T - 1) g_off[Nn] = ss[SCAN_T - 1];
}

__global__ void k_scatter(const int* __restrict__ ei) {
    int i = blockIdx.x * blockDim.x + threadIdx.x;
    if (i < Ee) {
        int src = ei[i];
        int d   = ei[Ee + i];
        int p = atomicAdd(&g_pos[d], 1);
        g_edges[p] = make_int2(i, src);
    }
}

// Fused: aggregation (segment softmax, no max pass) + residual + quaternion MLP.
// 16 threads per node; thread t owns component comp=t>>2, float4 slice f4=t&3.
// Block = 256 threads = 16 nodes.
__global__ void __launch_bounds__(256, 2)
k_main(const float* __restrict__ q, const float* __restrict__ ea,
       const float* __restrict__ W1, const float* __restrict__ b1,
       const float* __restrict__ W2, const float* __restrict__ b2,
       const float* __restrict__ beta_p, float* __restrict__ out)
{
    __shared__ float sW1[1024], sW2[1024], sb1[64], sb2[64];
    __shared__ float xs[16][64];

    int tid = threadIdx.x;
    for (int i = tid; i < 1024; i += 256) { sW1[i] = W1[i]; sW2[i] = W2[i]; }
    if (tid < 64) { sb1[tid] = b1[tid]; sb2[tid] = b2[tid]; }

    int ln   = tid >> 4;       // local node 0..15
    int t    = tid & 15;
    int node = blockIdx.x * 16 + ln;
    int comp = t >> 2;
    int f4   = t & 3;
    float beta = __ldg(beta_p);

    const float4* eav = (const float4*)(ea + (size_t)comp * Ee * Ff);
    const float4* qv  = (const float4*)(q  + (size_t)comp * Nn * Ff);

    float4 num = make_float4(0.f, 0.f, 0.f, 0.f);
    float4 den = make_float4(0.f, 0.f, 0.f, 0.f);

    int s = g_off[node];
    int e = g_off[node + 1];
#pragma unroll 4
    for (int i = s; i < e; i++) {
        int2 ed = __ldg(&g_edges[i]);
        float4 av = __ldg(&eav[ed.x * 4 + f4]);
        float4 qs = __ldg(&qv[ed.y * 4 + f4]);
        float m0 = av.x + qs.x, m1 = av.y + qs.y, m2 = av.z + qs.z, m3 = av.w + qs.w;
        float w0 = __expf(m0 * beta), w1 = __expf(m1 * beta);
        float w2 = __expf(m2 * beta), w3 = __expf(m3 * beta);
        num.x += m0 * w0; num.y += m1 * w1; num.z += m2 * w2; num.w += m3 * w3;
        den.x += w0;      den.y += w1;      den.z += w2;      den.w += w3;
    }

    float4 qself = __ldg(&qv[node * 4 + f4]);
    float4 x;
    x.x = qself.x + (den.x > 0.f ? num.x / den.x : 0.f);
    x.y = qself.y + (den.y > 0.f ? num.y / den.y : 0.f);
    x.z = qself.z + (den.z > 0.f ? num.z / den.z : 0.f);
    x.w = qself.w + (den.w > 0.f ? num.w / den.w : 0.f);

    __syncthreads();                 // weights staged; xs safe to write
    ((float4*)xs[ln])[t] = x;
    __syncthreads();

    // Quaternion sign table: e_a * e_b = SG[a][b] * e_{a^b}
    const float SG[4][4] = {
        { 1.f,  1.f,  1.f,  1.f},
        { 1.f, -1.f,  1.f, -1.f},
        { 1.f, -1.f, -1.f,  1.f},
        { 1.f,  1.f, -1.f, -1.f}
    };

    int fo = t;
    float wreg[64];

    // ---- layer 1 ----
#pragma unroll
    for (int b = 0; b < 4; b++)
#pragma unroll
        for (int fi = 0; fi < 16; fi++)
            wreg[b * 16 + fi] = sW1[b * 256 + fi * 16 + fo];

    float a0 = sb1[fo], a1 = sb1[16 + fo], a2 = sb1[32 + fo], a3 = sb1[48 + fo];
#pragma unroll
    for (int a = 0; a < 4; a++) {
#pragma unroll
        for (int fi = 0; fi < 16; fi++) {
            float xv = xs[ln][a * 16 + fi];
            a0 += SG[a][a ^ 0] * xv * wreg[(a ^ 0) * 16 + fi];
            a1 += SG[a][a ^ 1] * xv * wreg[(a ^ 1) * 16 + fi];
            a2 += SG[a][a ^ 2] * xv * wreg[(a ^ 2) * 16 + fi];
            a3 += SG[a][a ^ 3] * xv * wreg[(a ^ 3) * 16 + fi];
        }
    }
    a0 = fmaxf(a0, 0.f); a1 = fmaxf(a1, 0.f); a2 = fmaxf(a2, 0.f); a3 = fmaxf(a3, 0.f);

    __syncthreads();                 // all xs reads done
    xs[ln][fo]      = a0;
    xs[ln][16 + fo] = a1;
    xs[ln][32 + fo] = a2;
    xs[ln][48 + fo] = a3;
    __syncthreads();

    // ---- layer 2 ----
#pragma unroll
    for (int b = 0; b < 4; b++)
#pragma unroll
        for (int fi = 0; fi < 16; fi++)
            wreg[b * 16 + fi] = sW2[b * 256 + fi * 16 + fo];

    float c0 = sb2[fo], c1 = sb2[16 + fo], c2 = sb2[32 + fo], c3 = sb2[48 + fo];
#pragma unroll
    for (int a = 0; a < 4; a++) {
#pragma unroll
        for (int fi = 0; fi < 16; fi++) {
            float hv = xs[ln][a * 16 + fi];
            c0 += SG[a][a ^ 0] * hv * wreg[(a ^ 0) * 16 + fi];
            c1 += SG[a][a ^ 1] * hv * wreg[(a ^ 1) * 16 + fi];
            c2 += SG[a][a ^ 2] * hv * wreg[(a ^ 2) * 16 + fi];
            c3 += SG[a][a ^ 3] * hv * wreg[(a ^ 3) * 16 + fi];
        }
    }

    size_t plane = (size_t)Nn * Ff;
    size_t o = (size_t)node * Ff + fo;
    out[0 * plane + o] = c0;
    out[1 * plane + o] = c1;
    out[2 * plane + o] = c2;
    out[3 * plane + o] = c3;
}

extern "C" void kernel_launch(void* const* d_in, const int* in_sizes, int n_in,
                              void* d_out, int out_size) {
    const float* q    = (const float*)d_in[0];
    const float* ea   = (const float*)d_in[1];
    const int*   ei   = (const int*)d_in[2];
    const float* W1   = (const float*)d_in[3];
    const float* b1   = (const float*)d_in[4];
    const float* W2   = (const float*)d_in[5];
    const float* b2   = (const float*)d_in[6];
    const float* beta = (const float*)d_in[7];
    float* out = (float*)d_out;

    k_zero<<<(Nn + 511) / 512, 512>>>();
    k_hist<<<(Ee + 511) / 512, 512>>>(ei + Ee);     // dst row
    k_scan<<<1, SCAN_T>>>();
    k_scatter<<<(Ee + 511) / 512, 512>>>(ei);
    k_main<<<Nn / 16, 256>>>(q, ea, W1, b1, W2, b2, beta, out);
}

// round 6
// speedup vs baseline: 1.0268x; 1.0268x over previous
#include <cuda_runtime.h>

// QMessagePassing: N=50000 nodes, E=800000 edges, F=16 per quaternion component.
// CSR-by-dst build (int atomics only) + fused warp-per-node gather/softmax/MLP.

#define Nn 50000
#define Ee 800000
#define Ff 16

__device__ int  g_cnt[Nn];
__device__ int  g_off[Nn + 1];
__device__ int  g_pos[Nn];
__device__ int2 g_edges[Ee];   // (edge_id, src)

__global__ void k_zero() {
    int i = blockIdx.x * blockDim.x + threadIdx.x;
    if (i < Nn) g_cnt[i] = 0;
}

__global__ void k_hist(const int* __restrict__ dst) {
    int i = blockIdx.x * blockDim.x + threadIdx.x;
    if (i < Ee) atomicAdd(&g_cnt[dst[i]], 1);
}

#define SCAN_T 1024
#define SCAN_ITEMS 49   // 1024*49 = 50176 >= 50000
__global__ void k_scan() {
    __shared__ int ss[SCAN_T];
    int tid = threadIdx.x;
    int base = tid * SCAN_ITEMS;
    int loc[SCAN_ITEMS];
    int s = 0;
#pragma unroll
    for (int i = 0; i < SCAN_ITEMS; i++) {
        int idx = base + i;
        int v = (idx < Nn) ? g_cnt[idx] : 0;
        loc[i] = s;
        s += v;
    }
    ss[tid] = s;
    __syncthreads();
    for (int d = 1; d < SCAN_T; d <<= 1) {
        int v = (tid >= d) ? ss[tid - d] : 0;
        __syncthreads();
        ss[tid] += v;
        __syncthreads();
    }
    int prefix = (tid > 0) ? ss[tid - 1] : 0;
#pragma unroll
    for (int i = 0; i < SCAN_ITEMS; i++) {
        int idx = base + i;
        if (idx < Nn) {
            int o = prefix + loc[i];
            g_off[idx] = o;
            g_pos[idx] = o;
        }
    }
    if (tid == SCAN_T - 1) g_off[Nn] = ss[SCAN_T - 1];
}

__global__ void k_scatter(const int* __restrict__ ei) {
    int i = blockIdx.x * blockDim.x + threadIdx.x;
    if (i < Ee) {
        int src = ei[i];
        int d   = ei[Ee + i];
        int p = atomicAdd(&g_pos[d], 1);
        g_edges[p] = make_int2(i, src);
    }
}

// Warp-per-node: half-warps process even/odd edges, shfl-reduce, then the
// 32 lanes of the warp run the 2-layer quaternion MLP (2 outputs per lane).
// Sign mask: e_a*e_b = -e_{a^b} iff bit (a*4+b) of 0xC6A0 is set.
__global__ void __launch_bounds__(256, 3)
k_main(const float* __restrict__ q, const float* __restrict__ ea,
       const float* __restrict__ W1, const float* __restrict__ b1,
       const float* __restrict__ W2, const float* __restrict__ b2,
       const float* __restrict__ beta_p, float* __restrict__ out)
{
    __shared__ float sW1[1024], sW2[1024], sb1[64], sb2[64];
    __shared__ float xs[8][64];
    __shared__ float hs[8][64];

    int tid = threadIdx.x;
    for (int i = tid; i < 1024; i += 256) { sW1[i] = W1[i]; sW2[i] = W2[i]; }
    if (tid < 64) { sb1[tid] = b1[tid]; sb2[tid] = b2[tid]; }
    __syncthreads();

    int ln   = tid >> 5;           // warp = local node 0..7
    int lane = tid & 31;
    int node = blockIdx.x * 8 + ln;
    int half = lane >> 4;          // even/odd edge stream
    int t    = lane & 15;
    int comp = t >> 2;
    int f4   = t & 3;
    float beta = __ldg(beta_p);

    const float4* eav = (const float4*)(ea + (size_t)comp * Ee * Ff);
    const float4* qv  = (const float4*)(q  + (size_t)comp * Nn * Ff);

    float4 num = make_float4(0.f, 0.f, 0.f, 0.f);
    float4 den = make_float4(0.f, 0.f, 0.f, 0.f);

    int s = g_off[node];
    int e = g_off[node + 1];
#pragma unroll 4
    for (int i = s + half; i < e; i += 2) {
        int2 ed = __ldg(&g_edges[i]);
        float4 av = __ldg(&eav[ed.x * 4 + f4]);
        float4 qs = __ldg(&qv[ed.y * 4 + f4]);
        float m0 = av.x + qs.x, m1 = av.y + qs.y, m2 = av.z + qs.z, m3 = av.w + qs.w;
        float w0 = __expf(m0 * beta), w1 = __expf(m1 * beta);
        float w2 = __expf(m2 * beta), w3 = __expf(m3 * beta);
        num.x += m0 * w0; num.y += m1 * w1; num.z += m2 * w2; num.w += m3 * w3;
        den.x += w0;      den.y += w1;      den.z += w2;      den.w += w3;
    }

    // combine even/odd half-warp partials (lane ^ 16 holds same (comp,f4))
    num.x += __shfl_xor_sync(0xffffffffu, num.x, 16);
    num.y += __shfl_xor_sync(0xffffffffu, num.y, 16);
    num.z += __shfl_xor_sync(0xffffffffu, num.z, 16);
    num.w += __shfl_xor_sync(0xffffffffu, num.w, 16);
    den.x += __shfl_xor_sync(0xffffffffu, den.x, 16);
    den.y += __shfl_xor_sync(0xffffffffu, den.y, 16);
    den.z += __shfl_xor_sync(0xffffffffu, den.z, 16);
    den.w += __shfl_xor_sync(0xffffffffu, den.w, 16);

    if (lane < 16) {
        float4 qself = __ldg(&qv[node * 4 + f4]);
        float4 x;
        x.x = qself.x + (den.x > 0.f ? num.x / den.x : 0.f);
        x.y = qself.y + (den.y > 0.f ? num.y / den.y : 0.f);
        x.z = qself.z + (den.z > 0.f ? num.z / den.z : 0.f);
        x.w = qself.w + (den.w > 0.f ? num.w / den.w : 0.f);
        ((float4*)xs[ln])[t] = x;
    }
    __syncwarp();

    const unsigned SGM = 0xC6A0u;  // negative-sign bitmask for e_a*e_b
    int fo = lane & 15;
    int c1 = lane >> 4;     // components {0,1}
    int c2 = c1 + 2;        // components {2,3}
    float wreg[16];

    // ---- layer 1 ----
    float acc1 = sb1[c1 * 16 + fo];
    float acc2 = sb1[c2 * 16 + fo];
#pragma unroll
    for (int b = 0; b < 4; b++) {
#pragma unroll
        for (int fi = 0; fi < 16; fi++) wreg[fi] = sW1[b * 256 + fi * 16 + fo];
        int a1 = b ^ c1, a2 = b ^ c2;
        float d1 = 0.f, d2 = 0.f;
#pragma unroll
        for (int fi = 0; fi < 16; fi++) {
            d1 += xs[ln][a1 * 16 + fi] * wreg[fi];
            d2 += xs[ln][a2 * 16 + fi] * wreg[fi];
        }
        float s1 = ((SGM >> ((a1 << 2) | b)) & 1u) ? -1.f : 1.f;
        float s2 = ((SGM >> ((a2 << 2) | b)) & 1u) ? -1.f : 1.f;
        acc1 = fmaf(s1, d1, acc1);
        acc2 = fmaf(s2, d2, acc2);
    }
    hs[ln][c1 * 16 + fo] = fmaxf(acc1, 0.f);
    hs[ln][c2 * 16 + fo] = fmaxf(acc2, 0.f);
    __syncwarp();

    // ---- layer 2 ----
    float o1 = sb2[c1 * 16 + fo];
    float o2 = sb2[c2 * 16 + fo];
#pragma unroll
    for (int b = 0; b < 4; b++) {
#pragma unroll
        for (int fi = 0; fi < 16; fi++) wreg[fi] = sW2[b * 256 + fi * 16 + fo];
        int a1 = b ^ c1, a2 = b ^ c2;
        float d1 = 0.f, d2 = 0.f;
#pragma unroll
        for (int fi = 0; fi < 16; fi++) {
            d1 += hs[ln][a1 * 16 + fi] * wreg[fi];
            d2 += hs[ln][a2 * 16 + fi] * wreg[fi];
        }
        float s1 = ((SGM >> ((a1 << 2) | b)) & 1u) ? -1.f : 1.f;
        float s2 = ((SGM >> ((a2 << 2) | b)) & 1u) ? -1.f : 1.f;
        o1 = fmaf(s1, d1, o1);
        o2 = fmaf(s2, d2, o2);
    }

    size_t plane = (size_t)Nn * Ff;
    size_t o = (size_t)node * Ff + fo;
    out[(size_t)c1 * plane + o] = o1;
    out[(size_t)c2 * plane + o] = o2;
}

extern "C" void kernel_launch(void* const* d_in, const int* in_sizes, int n_in,
                              void* d_out, int out_size) {
    const float* q    = (const float*)d_in[0];
    const float* ea   = (const float*)d_in[1];
    const int*   ei   = (const int*)d_in[2];
    const float* W1   = (const float*)d_in[3];
    const float* b1   = (const float*)d_in[4];
    const float* W2   = (const float*)d_in[5];
    const float* b2   = (const float*)d_in[6];
    const float* beta = (const float*)d_in[7];
    float* out = (float*)d_out;

    k_zero<<<(Nn + 511) / 512, 512>>>();
    k_hist<<<(Ee + 511) / 512, 512>>>(ei + Ee);     // dst row
    k_scan<<<1, SCAN_T>>>();
    k_scatter<<<(Ee + 511) / 512, 512>>>(ei);
    k_main<<<Nn / 8, 256>>>(q, ea, W1, b1, W2, b2, beta, out);
}